// round 16
// baseline (speedup 1.0000x reference)
#include <cuda_runtime.h>
#include <cuda_bf16.h>
#include <cstdint>

// ---------------- problem constants ----------------
#define TT 8
#define BB 32
#define C1 128
#define H1 48
#define P1S 24
#define P2S 12
#define FC1_IN  (128*12*12)   // 18432
#define FC1_OUT 1152
#define FC2_OUT 128
#define FC3_OUT 7
#define NROWS (TT*BB)         // 256
#define MTOT  (NROWS*P1S*P1S) // 147456
#define SZW1  (FC1_OUT*FC1_IN)
#define NSLICE 16             // fc1 split-K slices

// ---------------- scratch ----------------
__device__ __nv_bfloat16 g_p1b[(size_t)MTOT*128];
__device__ float         g_c2[(size_t)MTOT*128];
__device__ __nv_bfloat16 g_s2[(size_t)NROWS*144*128];
__device__ __nv_bfloat16 g_w2s[3*9*128*128];
__device__ __nv_bfloat16 g_w1s[3ULL*SZW1];
__device__ float g_part1[NSLICE*NROWS*FC1_OUT];
__device__ float g_l1[NROWS*FC1_OUT];
__device__ float g_part2[8*NROWS*FC2_OUT];
__device__ float g_l2[NROWS*FC2_OUT];

// ---------------- packed f32x2 helpers ----------------
__device__ __forceinline__ unsigned long long ffma2(unsigned long long a,
                                                    unsigned long long b,
                                                    unsigned long long c) {
    unsigned long long d;
    asm("fma.rn.f32x2 %0, %1, %2, %3;" : "=l"(d) : "l"(a), "l"(b), "l"(c));
    return d;
}
__device__ __forceinline__ unsigned long long pk2(float lo, float hi) {
    unsigned long long r;
    asm("mov.b64 %0, {%1, %2};" : "=l"(r) : "f"(lo), "f"(hi));
    return r;
}
__device__ __forceinline__ float2 upk2(unsigned long long v) {
    float2 f;
    asm("mov.b64 {%0, %1}, %2;" : "=f"(f.x), "=f"(f.y) : "l"(v));
    return f;
}

// ---------------- mma / ldmatrix / cp.async helpers ----------------
__device__ __forceinline__ void hmma(float* d, const uint32_t* a, uint32_t b0, uint32_t b1) {
    asm volatile(
        "mma.sync.aligned.m16n8k16.row.col.f32.bf16.bf16.f32 "
        "{%0,%1,%2,%3}, {%4,%5,%6,%7}, {%8,%9}, {%0,%1,%2,%3};"
        : "+f"(d[0]), "+f"(d[1]), "+f"(d[2]), "+f"(d[3])
        : "r"(a[0]), "r"(a[1]), "r"(a[2]), "r"(a[3]), "r"(b0), "r"(b1));
}
__device__ __forceinline__ void ldsm4(uint32_t& r0, uint32_t& r1, uint32_t& r2, uint32_t& r3,
                                      uint32_t addr) {
    asm volatile("ldmatrix.sync.aligned.m8n8.x4.shared.b16 {%0,%1,%2,%3}, [%4];"
                 : "=r"(r0), "=r"(r1), "=r"(r2), "=r"(r3) : "r"(addr));
}
__device__ __forceinline__ void cpa16(uint32_t dst, const void* src, int srcsize) {
    asm volatile("cp.async.cg.shared.global [%0], [%1], 16, %2;"
                 :: "r"(dst), "l"(src), "r"(srcsize));
}
#define CP_COMMIT() asm volatile("cp.async.commit_group;" ::: "memory")
#define CP_WAIT0()  asm volatile("cp.async.wait_group 0;" ::: "memory")

// SW128 swizzle for 128B rows
__device__ __forceinline__ uint32_t swz(uint32_t off) { return off ^ ((off >> 3) & 0x70); }
__device__ __forceinline__ uint32_t smaddr(const void* p) {
    uint32_t a;
    asm("{ .reg .u64 t; cvta.to.shared.u64 t, %1; cvt.u32.u64 %0, t; }" : "=r"(a) : "l"(p));
    return a;
}

// ============================================================
// Prep: conv2 weight 3-split [s][koff][oc][ic]
// ============================================================
__global__ void k_prep_w2(const float* __restrict__ w2)
{
    int idx = blockIdx.x * blockDim.x + threadIdx.x;
    if (idx >= 128*128*9) return;
    int oc = idx / 1152;
    int r  = idx % 1152;
    int ic = r / 9, k = r % 9;
    float w = w2[idx];
    __nv_bfloat16 h = __float2bfloat16(w);
    float r1 = w - __bfloat162float(h);
    __nv_bfloat16 m = __float2bfloat16(r1);
    float r2 = r1 - __bfloat162float(m);
    __nv_bfloat16 l = __float2bfloat16(r2);
    size_t d = ((size_t)k*128 + oc)*128 + ic;
    g_w2s[d] = h;
    g_w2s[(size_t)9*128*128 + d] = m;
    g_w2s[(size_t)18*128*128 + d] = l;
}

// ============================================================
// Prep: fc1 weight 3-split + transpose to K' = p*128 + c.
// ============================================================
__global__ void __launch_bounds__(256) k_prep_w1(const float* __restrict__ w1)
{
    extern __shared__ float smw[];
    int n = blockIdx.x, tid = threadIdx.x;
    const float4* src = (const float4*)(w1 + (size_t)n*FC1_IN);
#pragma unroll
    for (int l = 0; l < 18; l++) {
        int i = tid + l*256;
        float4 v = src[i];
        int idx = i*4;
        int c = idx / 144, p = idx - c*144;
        float* d = &smw[c*145 + p];
        d[0] = v.x; d[1] = v.y; d[2] = v.z; d[3] = v.w;
    }
    __syncthreads();
    __nv_bfloat16* o0 = g_w1s + (size_t)n*FC1_IN;
    __nv_bfloat16* o1 = o0 + (size_t)SZW1;
    __nv_bfloat16* o2 = o0 + 2*(size_t)SZW1;
#pragma unroll
    for (int l = 0; l < 72; l++) {
        int j = tid + l*256;
        int p = j >> 7, c = j & 127;
        float w = smw[c*145 + p];
        __nv_bfloat16 h = __float2bfloat16(w);
        float r1 = w - __bfloat162float(h);
        __nv_bfloat16 m = __float2bfloat16(r1);
        float r2 = r1 - __bfloat162float(m);
        o0[j] = h;
        o1[j] = m;
        o2[j] = __float2bfloat16(r2);
    }
}

// ============================================================
// conv1 + BN1 + IF + pool -> g_p1b (NHWC bf16 spikes)
// ============================================================
__global__ void k_conv1_if_pool(const float* __restrict__ x,
                                const float* __restrict__ w1,
                                const float* __restrict__ b1,
                                const float* __restrict__ bg,
                                const float* __restrict__ bbta,
                                const float* __restrict__ bm,
                                const float* __restrict__ bv)
{
    int idx = blockIdx.x * blockDim.x + threadIdx.x;
    if (idx >= BB*P1S*P1S*128) return;
    int c   = idx & 127;
    int pos = idx >> 7;
    int b   = pos / (P1S*P1S);
    int p   = pos % (P1S*P1S);
    int py = p / P1S, px = p % P1S;

    float w[9];
#pragma unroll
    for (int k = 0; k < 9; k++) w[k] = w1[c*9 + k];
    float scale = bg[c] * rsqrtf(bv[c] + 1e-5f);
    float add   = (b1[c] - bm[c]) * scale + bbta[c];

    const float* xb = x + b*H1*H1;
    float h[4];
#pragma unroll
    for (int d = 0; d < 4; d++) {
        int y  = 2*py + (d >> 1);
        int xx = 2*px + (d & 1);
        float s = 0.f;
#pragma unroll
        for (int ky = 0; ky < 3; ky++) {
            int gy = y + ky - 1;
            if (gy < 0 || gy >= H1) continue;
#pragma unroll
            for (int kx = 0; kx < 3; kx++) {
                int gx = xx + kx - 1;
                if (gx < 0 || gx >= H1) continue;
                s += xb[gy*H1 + gx] * w[ky*3 + kx];
            }
        }
        h[d] = s * scale + add;
    }

    float v[4] = {0.f, 0.f, 0.f, 0.f};
#pragma unroll
    for (int t = 0; t < TT; t++) {
        float any = 0.f;
#pragma unroll
        for (int d = 0; d < 4; d++) {
            v[d] += h[d];
            if (v[d] >= 1.0f) { any = 1.f; v[d] = 0.f; }
        }
        g_p1b[((size_t)(t*BB + b)*576 + p)*128 + c] = __float2bfloat16(any);
    }
}

// ============================================================
// conv2 HMMA GEMM (frozen round-8 structure, 77% tensor).
// ============================================================
__global__ void __launch_bounds__(256, 2) k_conv2_mma()
{
    extern __shared__ unsigned char dsm[];
    uint32_t sb0 = smaddr(dsm);
    uint32_t sb  = (sb0 + 1023) & ~1023u;

    int tid = threadIdx.x, wid = tid >> 5, lane = tid & 31;
    int wm = wid & 3, wn = wid >> 2;
    int mbase = blockIdx.x * 128;

    uint32_t a_base[2], a_xor[2];
#pragma unroll
    for (int mi = 0; mi < 2; mi++) {
        int r = wm*32 + mi*16 + (lane & 15);
        a_base[mi] = sb + (uint32_t)(r*128);
        a_xor[mi]  = (uint32_t)((r & 7) << 4);
    }
    uint32_t a_kbsel = (uint32_t)((lane >> 4) * 16);
    int b_rl = ((lane >> 4) & 1)*8 + (lane & 7);
    uint32_t b_kbsel = (uint32_t)(((lane >> 3) & 1) * 16);

    float acc[2][8][4];
#pragma unroll
    for (int i = 0; i < 2; i++)
#pragma unroll
        for (int j = 0; j < 8; j++)
#pragma unroll
            for (int k = 0; k < 4; k++) acc[i][j][k] = 0.f;

    for (int koff = 0; koff < 9; koff++) {
        int ky = koff/3 - 1, kx = koff%3 - 1;
        for (int icc = 0; icc < 2; icc++) {
#pragma unroll
            for (int l = 0; l < 4; l++) {
                int e = tid + l*256;
                int r = e >> 3, ln = e & 7;
                int m = mbase + r;
                int img = m / 576;
                int pix = m - img*576;
                int y = pix / 24, x = pix - y*24;
                int gy = y + ky, gx = x + kx;
                int inb = ((unsigned)gy < 24u && (unsigned)gx < 24u);
                const void* src = inb
                    ? (const void*)(g_p1b + ((size_t)(img*576 + gy*24 + gx)*128 + icc*64 + ln*8))
                    : (const void*)g_p1b;
                cpa16(sb + swz((uint32_t)(r*128 + ln*16)), src, inb ? 16 : 0);
            }
#pragma unroll
            for (int l = 0; l < 12; l++) {
                int e = tid + l*256;
                int s = e >> 10, r = (e >> 3) & 127, ln = e & 7;
                const void* src = g_w2s + ((size_t)((s*9 + koff)*128 + r)*128 + icc*64 + ln*8);
                cpa16(sb + 16384u + (uint32_t)(s*16384) + swz((uint32_t)(r*128 + ln*16)), src, 16);
            }
            CP_COMMIT();
            CP_WAIT0();
            __syncthreads();

#pragma unroll
            for (int kk = 0; kk < 4; kk++) {
                uint32_t akb = (uint32_t)(kk*32) + a_kbsel;
                uint32_t a[2][4];
#pragma unroll
                for (int mi = 0; mi < 2; mi++)
                    ldsm4(a[mi][0], a[mi][1], a[mi][2], a[mi][3],
                          a_base[mi] + (akb ^ a_xor[mi]));
                uint32_t bkb = (uint32_t)(kk*32) + b_kbsel;
#pragma unroll
                for (int s = 0; s < 3; s++) {
                    uint32_t bs = sb + 16384u + (uint32_t)(s*16384);
#pragma unroll
                    for (int jp = 0; jp < 4; jp++) {
                        int rb = wn*64 + jp*16 + b_rl;
                        uint32_t b0, b1, b2, b3;
                        ldsm4(b0, b1, b2, b3,
                              bs + (uint32_t)(rb*128) + (bkb ^ (uint32_t)((rb & 7) << 4)));
                        hmma(acc[0][2*jp],   a[0], b0, b1);
                        hmma(acc[1][2*jp],   a[1], b0, b1);
                        hmma(acc[0][2*jp+1], a[0], b2, b3);
                        hmma(acc[1][2*jp+1], a[1], b2, b3);
                    }
                }
            }
            __syncthreads();
        }
    }

    int gid = lane >> 2, qid = lane & 3;
#pragma unroll
    for (int mi = 0; mi < 2; mi++) {
        int m = mbase + wm*32 + mi*16 + gid;
#pragma unroll
        for (int ni = 0; ni < 8; ni++) {
            int n = wn*64 + ni*8 + qid*2;
            *(float2*)(g_c2 + (size_t)m*128 + n)     = make_float2(acc[mi][ni][0], acc[mi][ni][1]);
            *(float2*)(g_c2 + (size_t)(m+8)*128 + n) = make_float2(acc[mi][ni][2], acc[mi][ni][3]);
        }
    }
}

// ============================================================
// BN2 + IF + pool -> g_s2
// ============================================================
__global__ void k_if2_pool(const float* __restrict__ b2,
                           const float* __restrict__ bg,
                           const float* __restrict__ bbta,
                           const float* __restrict__ bm,
                           const float* __restrict__ bv)
{
    int pos = blockIdx.x;
    int b = pos / 144, pp = pos % 144;
    int py = pp / 12, px = pp % 12;
    int oc = threadIdx.x;

    float scale = bg[oc] * rsqrtf(bv[oc] + 1e-5f);
    float add   = (b2[oc] - bm[oc]) * scale + bbta[oc];

    float v[4] = {0.f, 0.f, 0.f, 0.f};
#pragma unroll
    for (int t = 0; t < TT; t++) {
        float any = 0.f;
#pragma unroll
        for (int d = 0; d < 4; d++) {
            int m = (t*BB + b)*576 + (2*py + (d>>1))*24 + (2*px + (d&1));
            float xx = g_c2[(size_t)m*128 + oc] * scale + add;
            v[d] += xx;
            if (v[d] >= 1.0f) { any = 1.f; v[d] = 0.f; }
        }
        g_s2[((size_t)(t*BB + b)*144 + pp)*128 + oc] = __float2bfloat16(any);
    }
}

// ============================================================
// fc1 HMMA GEMM, split-K=16, FULL-M blocks (M=256, 512 threads,
// 8 M-warps x 2 N-warps): each B tile is read exactly ONCE.
// grid (9 n-tiles, 16 slices) = 144 blocks.
// Smem/stage: A 32KB @0, B 3x16KB @32KB.
// ============================================================
__global__ void __launch_bounds__(512, 1) k_fc1_mma()
{
    extern __shared__ unsigned char dsm[];
    uint32_t sb0 = smaddr(dsm);
    uint32_t sb  = (sb0 + 1023) & ~1023u;

    int tid = threadIdx.x, wid = tid >> 5, lane = tid & 31;
    int wm = wid & 7, wn = wid >> 3;

    int nbase = blockIdx.x * 128;
    int slice = blockIdx.y;
    int kbase = slice * (FC1_IN/NSLICE);   // 1152

    uint32_t a_base[2], a_xor[2];
#pragma unroll
    for (int mi = 0; mi < 2; mi++) {
        int r = wm*32 + mi*16 + (lane & 15);          // 0..255
        a_base[mi] = sb + (uint32_t)(r*128);
        a_xor[mi]  = (uint32_t)((r & 7) << 4);
    }
    uint32_t a_kbsel = (uint32_t)((lane >> 4) * 16);
    int b_rl = ((lane >> 4) & 1)*8 + (lane & 7);
    uint32_t b_kbsel = (uint32_t)(((lane >> 3) & 1) * 16);

    float acc[2][8][4];
#pragma unroll
    for (int i = 0; i < 2; i++)
#pragma unroll
        for (int j = 0; j < 8; j++)
#pragma unroll
            for (int k = 0; k < 4; k++) acc[i][j][k] = 0.f;

    for (int c = 0; c < 18; c++) {
        int k0 = kbase + c*64;
        // ---- stage A: 256 rows x 64 k = 2048 chunks ----
#pragma unroll
        for (int l = 0; l < 4; l++) {
            int e = tid + l*512;
            int r = e >> 3, ln = e & 7;
            const void* src = g_s2 + (size_t)r*FC1_IN + k0 + ln*8;
            cpa16(sb + swz((uint32_t)(r*128 + ln*16)), src, 16);
        }
        // ---- stage B: 3 splits x 128 n x 64 k = 3072 chunks ----
#pragma unroll
        for (int l = 0; l < 6; l++) {
            int e = tid + l*512;
            int s = e >> 10, r = (e >> 3) & 127, ln = e & 7;
            const void* src = g_w1s + ((size_t)s*SZW1 + (size_t)(nbase + r)*FC1_IN + k0 + ln*8);
            cpa16(sb + 32768u + (uint32_t)(s*16384) + swz((uint32_t)(r*128 + ln*16)), src, 16);
        }
        CP_COMMIT();
        CP_WAIT0();
        __syncthreads();

#pragma unroll
        for (int kk = 0; kk < 4; kk++) {
            uint32_t akb = (uint32_t)(kk*32) + a_kbsel;
            uint32_t a[2][4];
#pragma unroll
            for (int mi = 0; mi < 2; mi++)
                ldsm4(a[mi][0], a[mi][1], a[mi][2], a[mi][3],
                      a_base[mi] + (akb ^ a_xor[mi]));
            uint32_t bkb = (uint32_t)(kk*32) + b_kbsel;
#pragma unroll
            for (int s = 0; s < 3; s++) {
                uint32_t bs = sb + 32768u + (uint32_t)(s*16384);
#pragma unroll
                for (int jp = 0; jp < 4; jp++) {
                    int rb = wn*64 + jp*16 + b_rl;
                    uint32_t b0, b1, b2, b3;
                    ldsm4(b0, b1, b2, b3,
                          bs + (uint32_t)(rb*128) + (bkb ^ (uint32_t)((rb & 7) << 4)));
                    hmma(acc[0][2*jp],   a[0], b0, b1);
                    hmma(acc[1][2*jp],   a[1], b0, b1);
                    hmma(acc[0][2*jp+1], a[0], b2, b3);
                    hmma(acc[1][2*jp+1], a[1], b2, b3);
                }
            }
        }
        __syncthreads();
    }

    int gid = lane >> 2, qid = lane & 3;
#pragma unroll
    for (int mi = 0; mi < 2; mi++) {
        int m = wm*32 + mi*16 + gid;
#pragma unroll
        for (int ni = 0; ni < 8; ni++) {
            int n = nbase + wn*64 + ni*8 + qid*2;
            float* dst = g_part1 + ((size_t)slice*NROWS + m)*FC1_OUT + n;
            *(float2*)dst = make_float2(acc[mi][ni][0], acc[mi][ni][1]);
            *(float2*)(dst + 8*FC1_OUT) = make_float2(acc[mi][ni][2], acc[mi][ni][3]);
        }
    }
}

// ============================================================
// fc2 scalar FFMA2 GEMM
// ============================================================
__global__ void __launch_bounds__(256)
k_gemm2(const float* __restrict__ Bmat, int N, int K, int klen)
{
    __shared__ float AsT[16][130];
    __shared__ float BsT[16][66];
    const float* A = g_l1;
    float* P = g_part2;

    int tid = threadIdx.x;
    int tx = tid & 15, ty = tid >> 4;
    int bm = blockIdx.y, bn = blockIdx.x, sz = blockIdx.z;
    int ks = sz * klen, ke = ks + klen;

    unsigned long long acc[4][4];
#pragma unroll
    for (int i = 0; i < 4; i++)
#pragma unroll
        for (int j = 0; j < 4; j++) acc[i][j] = 0ULL;

    for (int kk = ks; kk < ke; kk += 16) {
#pragma unroll
        for (int l = 0; l < 2; l++) {
            int lin = tid + l*256;
            int row = lin >> 2, cg = lin & 3;
            const float4 va = *reinterpret_cast<const float4*>(
                &A[(size_t)(bm*128 + row)*K + kk + cg*4]);
            AsT[cg*4 + 0][row] = va.x; AsT[cg*4 + 1][row] = va.y;
            AsT[cg*4 + 2][row] = va.z; AsT[cg*4 + 3][row] = va.w;
        }
        {
            int row = tid >> 2, cg = tid & 3;
            const float4 vb = *reinterpret_cast<const float4*>(
                &Bmat[(size_t)(bn*64 + row)*K + kk + cg*4]);
            BsT[cg*4 + 0][row] = vb.x; BsT[cg*4 + 1][row] = vb.y;
            BsT[cg*4 + 2][row] = vb.z; BsT[cg*4 + 3][row] = vb.w;
        }
        __syncthreads();
#pragma unroll
        for (int c = 0; c < 16; c++) {
            unsigned long long a2[4];
#pragma unroll
            for (int ip = 0; ip < 4; ip++)
                a2[ip] = *reinterpret_cast<const unsigned long long*>(&AsT[c][ty*8 + ip*2]);
            unsigned long long b2[4];
#pragma unroll
            for (int j = 0; j < 4; j++) {
                float bv = BsT[c][tx*4 + j];
                b2[j] = pk2(bv, bv);
            }
#pragma unroll
            for (int ip = 0; ip < 4; ip++)
#pragma unroll
                for (int j = 0; j < 4; j++)
                    acc[ip][j] = ffma2(a2[ip], b2[j], acc[ip][j]);
        }
        __syncthreads();
    }
#pragma unroll
    for (int ip = 0; ip < 4; ip++)
#pragma unroll
        for (int j = 0; j < 4; j++) {
            float2 u = upk2(acc[ip][j]);
            int row = bm*128 + ty*8 + ip*2;
            int col = bn*64 + tx*4 + j;
            P[(size_t)sz*NROWS*N + (size_t)row*N + col] = u.x;
            P[(size_t)sz*NROWS*N + (size_t)(row+1)*N + col] = u.y;
        }
}

// ============================================================
// Fused: split-K reduce + bias + LIF
// ============================================================
__global__ void k_reduce_lif(const float* __restrict__ bias, int which, int N, int S)
{
    const float* P = (which == 0) ? g_part1 : g_part2;
    float* L       = (which == 0) ? g_l1 : g_l2;
    int idx = blockIdx.x * blockDim.x + threadIdx.x;
    if (idx >= BB*N) return;
    int b = idx / N, o = idx % N;
    float bo = bias[o];
    float v = 0.f;
#pragma unroll 2
    for (int t = 0; t < TT; t++) {
        float s = bo;
        size_t base = (size_t)(t*BB + b)*N + o;
        for (int z = 0; z < S; z++) s += P[(size_t)z*NROWS*N + base];
        v += (s - v) * 0.5f;
        float sp = (v >= 1.0f) ? 1.f : 0.f;
        L[base] = sp;
        if (sp != 0.f) v = 0.f;
    }
}

// fc3 + LIF + mean over T
__global__ void k_fc3_lif_mean(const float* __restrict__ w,
                               const float* __restrict__ bias,
                               float* __restrict__ out)
{
    __shared__ float row[FC2_OUT];
    int b = blockIdx.x, tid = threadIdx.x;
    float v = 0.f, acc = 0.f;
#pragma unroll
    for (int t = 0; t < TT; t++) {
        for (int i = tid; i < FC2_OUT; i += 32)
            row[i] = g_l2[(size_t)(t*BB + b)*FC2_OUT + i];
        __syncthreads();
        if (tid < FC3_OUT) {
            float s = bias[tid];
#pragma unroll 8
            for (int i = 0; i < FC2_OUT; i++) s += row[i] * w[tid*FC2_OUT + i];
            v += (s - v) * 0.5f;
            if (v >= 1.0f) { acc += 1.f; v = 0.f; }
        }
        __syncthreads();
    }
    if (tid < FC3_OUT) out[b*FC3_OUT + tid] = acc * 0.125f;
}

// ============================================================
extern "C" void kernel_launch(void* const* d_in, const int* in_sizes, int n_in,
                              void* d_out, int out_size)
{
    const float* x       = (const float*)d_in[0];
    const float* conv1_w = (const float*)d_in[1];
    const float* conv1_b = (const float*)d_in[2];
    const float* bn1_g   = (const float*)d_in[3];
    const float* bn1_b   = (const float*)d_in[4];
    const float* bn1_m   = (const float*)d_in[5];
    const float* bn1_v   = (const float*)d_in[6];
    const float* conv2_w = (const float*)d_in[7];
    const float* conv2_b = (const float*)d_in[8];
    const float* bn2_g   = (const float*)d_in[9];
    const float* bn2_b   = (const float*)d_in[10];
    const float* bn2_m   = (const float*)d_in[11];
    const float* bn2_v   = (const float*)d_in[12];
    const float* fc1_w   = (const float*)d_in[13];
    const float* fc1_b   = (const float*)d_in[14];
    const float* fc2_w   = (const float*)d_in[15];
    const float* fc2_b   = (const float*)d_in[16];
    const float* fc3_w   = (const float*)d_in[17];
    const float* fc3_b   = (const float*)d_in[18];
    float* out = (float*)d_out;

    const int DSM    = 66560;           // conv2: 64KB tiles + 1KB align slack
    const int DSM_F1 = 82944;           // fc1: 80KB tiles + 1KB align slack
    const int PW1_SMEM = 128*145*4;     // 74240
    cudaFuncSetAttribute(k_conv2_mma, cudaFuncAttributeMaxDynamicSharedMemorySize, DSM);
    cudaFuncSetAttribute(k_fc1_mma,  cudaFuncAttributeMaxDynamicSharedMemorySize, DSM_F1);
    cudaFuncSetAttribute(k_prep_w1,  cudaFuncAttributeMaxDynamicSharedMemorySize, PW1_SMEM);

    // ---- side stream for weight prep (capture-safe fork/join) ----
    cudaStream_t s1;
    cudaStreamCreateWithFlags(&s1, cudaStreamNonBlocking);
    cudaEvent_t eFork, eW2, eW1;
    cudaEventCreateWithFlags(&eFork, cudaEventDisableTiming);
    cudaEventCreateWithFlags(&eW2,   cudaEventDisableTiming);
    cudaEventCreateWithFlags(&eW1,   cudaEventDisableTiming);

    cudaEventRecord(eFork, 0);
    cudaStreamWaitEvent(s1, eFork, 0);

    // side stream: weight prep
    k_prep_w2<<<(128*128*9 + 255)/256, 256, 0, s1>>>(conv2_w);
    cudaEventRecord(eW2, s1);
    k_prep_w1<<<FC1_OUT, 256, PW1_SMEM, s1>>>(fc1_w);
    cudaEventRecord(eW1, s1);

    // main stream
    {
        int total = BB*P1S*P1S*128;
        k_conv1_if_pool<<<(total + 255)/256, 256>>>(x, conv1_w, conv1_b,
                                                    bn1_g, bn1_b, bn1_m, bn1_v);
    }
    cudaStreamWaitEvent(0, eW2, 0);
    k_conv2_mma<<<MTOT/128, 256, DSM>>>();
    k_if2_pool<<<BB*144, 128>>>(conv2_b, bn2_g, bn2_b, bn2_m, bn2_v);
    cudaStreamWaitEvent(0, eW1, 0);
    {
        dim3 g(FC1_OUT/128, NSLICE);
        k_fc1_mma<<<g, 512, DSM_F1>>>();
        int n = BB*FC1_OUT;
        k_reduce_lif<<<(n + 255)/256, 256>>>(fc1_b, 0, FC1_OUT, NSLICE);
    }
    {
        dim3 g(FC2_OUT/64, NROWS/128, 8);
        k_gemm2<<<g, 256>>>(fc2_w, FC2_OUT, FC1_OUT, FC1_OUT/8);
        int n = BB*FC2_OUT;
        k_reduce_lif<<<(n + 255)/256, 256>>>(fc2_b, 1, FC2_OUT, 8);
    }
    k_fc3_lif_mean<<<BB, 32>>>(fc3_w, fc3_b, out);
}

// round 17
// speedup vs baseline: 1.0234x; 1.0234x over previous
#include <cuda_runtime.h>
#include <cuda_bf16.h>
#include <cstdint>

// ---------------- problem constants ----------------
#define TT 8
#define BB 32
#define C1 128
#define H1 48
#define P1S 24
#define P2S 12
#define FC1_IN  (128*12*12)   // 18432
#define FC1_OUT 1152
#define FC2_OUT 128
#define FC3_OUT 7
#define NROWS (TT*BB)         // 256
#define MTOT  (NROWS*P1S*P1S) // 147456
#define SZW1  (FC1_OUT*FC1_IN)
#define NSLICE 16             // fc1 split-K slices

// ---------------- scratch ----------------
__device__ __nv_bfloat16 g_p1b[(size_t)MTOT*128];
__device__ float         g_c2[(size_t)MTOT*128];
__device__ __nv_bfloat16 g_s2[(size_t)NROWS*144*128];
__device__ __nv_bfloat16 g_w2s[3*9*128*128];
__device__ __nv_bfloat16 g_w1s[3ULL*SZW1];
__device__ float g_part1[NSLICE*NROWS*FC1_OUT];
__device__ float g_l1[NROWS*FC1_OUT];
__device__ float g_part2[8*NROWS*FC2_OUT];
__device__ float g_l2[NROWS*FC2_OUT];

// ---------------- packed f32x2 helpers ----------------
__device__ __forceinline__ unsigned long long ffma2(unsigned long long a,
                                                    unsigned long long b,
                                                    unsigned long long c) {
    unsigned long long d;
    asm("fma.rn.f32x2 %0, %1, %2, %3;" : "=l"(d) : "l"(a), "l"(b), "l"(c));
    return d;
}
__device__ __forceinline__ unsigned long long pk2(float lo, float hi) {
    unsigned long long r;
    asm("mov.b64 %0, {%1, %2};" : "=l"(r) : "f"(lo), "f"(hi));
    return r;
}
__device__ __forceinline__ float2 upk2(unsigned long long v) {
    float2 f;
    asm("mov.b64 {%0, %1}, %2;" : "=f"(f.x), "=f"(f.y) : "l"(v));
    return f;
}

// ---------------- mma / ldmatrix / cp.async helpers ----------------
__device__ __forceinline__ void hmma(float* d, const uint32_t* a, uint32_t b0, uint32_t b1) {
    asm volatile(
        "mma.sync.aligned.m16n8k16.row.col.f32.bf16.bf16.f32 "
        "{%0,%1,%2,%3}, {%4,%5,%6,%7}, {%8,%9}, {%0,%1,%2,%3};"
        : "+f"(d[0]), "+f"(d[1]), "+f"(d[2]), "+f"(d[3])
        : "r"(a[0]), "r"(a[1]), "r"(a[2]), "r"(a[3]), "r"(b0), "r"(b1));
}
__device__ __forceinline__ void ldsm4(uint32_t& r0, uint32_t& r1, uint32_t& r2, uint32_t& r3,
                                      uint32_t addr) {
    asm volatile("ldmatrix.sync.aligned.m8n8.x4.shared.b16 {%0,%1,%2,%3}, [%4];"
                 : "=r"(r0), "=r"(r1), "=r"(r2), "=r"(r3) : "r"(addr));
}
__device__ __forceinline__ void cpa16(uint32_t dst, const void* src, int srcsize) {
    asm volatile("cp.async.cg.shared.global [%0], [%1], 16, %2;"
                 :: "r"(dst), "l"(src), "r"(srcsize));
}
#define CP_COMMIT() asm volatile("cp.async.commit_group;" ::: "memory")
#define CP_WAIT1()  asm volatile("cp.async.wait_group 1;" ::: "memory")
#define CP_WAIT0()  asm volatile("cp.async.wait_group 0;" ::: "memory")

// swizzles
__device__ __forceinline__ uint32_t swz(uint32_t off)   { return off ^ ((off >> 3) & 0x70); } // 128B rows
__device__ __forceinline__ uint32_t swz64(uint32_t off) { return off ^ ((off >> 3) & 0x30); } // 64B rows
__device__ __forceinline__ uint32_t smaddr(const void* p) {
    uint32_t a;
    asm("{ .reg .u64 t; cvta.to.shared.u64 t, %1; cvt.u32.u64 %0, t; }" : "=r"(a) : "l"(p));
    return a;
}

// fc1 pipeline constants
#define F1_STAGE 40960        // A 16KB + 3xB 8KB
#define F1_BOFF  16384

// ============================================================
// Prep: conv2 weight 3-split [s][koff][oc][ic]
// ============================================================
__global__ void k_prep_w2(const float* __restrict__ w2)
{
    int idx = blockIdx.x * blockDim.x + threadIdx.x;
    if (idx >= 128*128*9) return;
    int oc = idx / 1152;
    int r  = idx % 1152;
    int ic = r / 9, k = r % 9;
    float w = w2[idx];
    __nv_bfloat16 h = __float2bfloat16(w);
    float r1 = w - __bfloat162float(h);
    __nv_bfloat16 m = __float2bfloat16(r1);
    float r2 = r1 - __bfloat162float(m);
    __nv_bfloat16 l = __float2bfloat16(r2);
    size_t d = ((size_t)k*128 + oc)*128 + ic;
    g_w2s[d] = h;
    g_w2s[(size_t)9*128*128 + d] = m;
    g_w2s[(size_t)18*128*128 + d] = l;
}

// ============================================================
// Prep: fc1 weight 3-split + transpose to K' = p*128 + c.
// ============================================================
__global__ void __launch_bounds__(256) k_prep_w1(const float* __restrict__ w1)
{
    extern __shared__ float smw[];
    int n = blockIdx.x, tid = threadIdx.x;
    const float4* src = (const float4*)(w1 + (size_t)n*FC1_IN);
#pragma unroll
    for (int l = 0; l < 18; l++) {
        int i = tid + l*256;
        float4 v = src[i];
        int idx = i*4;
        int c = idx / 144, p = idx - c*144;
        float* d = &smw[c*145 + p];
        d[0] = v.x; d[1] = v.y; d[2] = v.z; d[3] = v.w;
    }
    __syncthreads();
    __nv_bfloat16* o0 = g_w1s + (size_t)n*FC1_IN;
    __nv_bfloat16* o1 = o0 + (size_t)SZW1;
    __nv_bfloat16* o2 = o0 + 2*(size_t)SZW1;
#pragma unroll
    for (int l = 0; l < 72; l++) {
        int j = tid + l*256;
        int p = j >> 7, c = j & 127;
        float w = smw[c*145 + p];
        __nv_bfloat16 h = __float2bfloat16(w);
        float r1 = w - __bfloat162float(h);
        __nv_bfloat16 m = __float2bfloat16(r1);
        float r2 = r1 - __bfloat162float(m);
        o0[j] = h;
        o1[j] = m;
        o2[j] = __float2bfloat16(r2);
    }
}

// ============================================================
// conv1 + BN1 + IF + pool -> g_p1b (NHWC bf16 spikes)
// ============================================================
__global__ void k_conv1_if_pool(const float* __restrict__ x,
                                const float* __restrict__ w1,
                                const float* __restrict__ b1,
                                const float* __restrict__ bg,
                                const float* __restrict__ bbta,
                                const float* __restrict__ bm,
                                const float* __restrict__ bv)
{
    int idx = blockIdx.x * blockDim.x + threadIdx.x;
    if (idx >= BB*P1S*P1S*128) return;
    int c   = idx & 127;
    int pos = idx >> 7;
    int b   = pos / (P1S*P1S);
    int p   = pos % (P1S*P1S);
    int py = p / P1S, px = p % P1S;

    float w[9];
#pragma unroll
    for (int k = 0; k < 9; k++) w[k] = w1[c*9 + k];
    float scale = bg[c] * rsqrtf(bv[c] + 1e-5f);
    float add   = (b1[c] - bm[c]) * scale + bbta[c];

    const float* xb = x + b*H1*H1;
    float h[4];
#pragma unroll
    for (int d = 0; d < 4; d++) {
        int y  = 2*py + (d >> 1);
        int xx = 2*px + (d & 1);
        float s = 0.f;
#pragma unroll
        for (int ky = 0; ky < 3; ky++) {
            int gy = y + ky - 1;
            if (gy < 0 || gy >= H1) continue;
#pragma unroll
            for (int kx = 0; kx < 3; kx++) {
                int gx = xx + kx - 1;
                if (gx < 0 || gx >= H1) continue;
                s += xb[gy*H1 + gx] * w[ky*3 + kx];
            }
        }
        h[d] = s * scale + add;
    }

    float v[4] = {0.f, 0.f, 0.f, 0.f};
#pragma unroll
    for (int t = 0; t < TT; t++) {
        float any = 0.f;
#pragma unroll
        for (int d = 0; d < 4; d++) {
            v[d] += h[d];
            if (v[d] >= 1.0f) { any = 1.f; v[d] = 0.f; }
        }
        g_p1b[((size_t)(t*BB + b)*576 + p)*128 + c] = __float2bfloat16(any);
    }
}

// ============================================================
// conv2 HMMA GEMM (frozen round-8 structure, 77% tensor).
// ============================================================
__global__ void __launch_bounds__(256, 2) k_conv2_mma()
{
    extern __shared__ unsigned char dsm[];
    uint32_t sb0 = smaddr(dsm);
    uint32_t sb  = (sb0 + 1023) & ~1023u;

    int tid = threadIdx.x, wid = tid >> 5, lane = tid & 31;
    int wm = wid & 3, wn = wid >> 2;
    int mbase = blockIdx.x * 128;

    uint32_t a_base[2], a_xor[2];
#pragma unroll
    for (int mi = 0; mi < 2; mi++) {
        int r = wm*32 + mi*16 + (lane & 15);
        a_base[mi] = sb + (uint32_t)(r*128);
        a_xor[mi]  = (uint32_t)((r & 7) << 4);
    }
    uint32_t a_kbsel = (uint32_t)((lane >> 4) * 16);
    int b_rl = ((lane >> 4) & 1)*8 + (lane & 7);
    uint32_t b_kbsel = (uint32_t)(((lane >> 3) & 1) * 16);

    float acc[2][8][4];
#pragma unroll
    for (int i = 0; i < 2; i++)
#pragma unroll
        for (int j = 0; j < 8; j++)
#pragma unroll
            for (int k = 0; k < 4; k++) acc[i][j][k] = 0.f;

    for (int koff = 0; koff < 9; koff++) {
        int ky = koff/3 - 1, kx = koff%3 - 1;
        for (int icc = 0; icc < 2; icc++) {
#pragma unroll
            for (int l = 0; l < 4; l++) {
                int e = tid + l*256;
                int r = e >> 3, ln = e & 7;
                int m = mbase + r;
                int img = m / 576;
                int pix = m - img*576;
                int y = pix / 24, x = pix - y*24;
                int gy = y + ky, gx = x + kx;
                int inb = ((unsigned)gy < 24u && (unsigned)gx < 24u);
                const void* src = inb
                    ? (const void*)(g_p1b + ((size_t)(img*576 + gy*24 + gx)*128 + icc*64 + ln*8))
                    : (const void*)g_p1b;
                cpa16(sb + swz((uint32_t)(r*128 + ln*16)), src, inb ? 16 : 0);
            }
#pragma unroll
            for (int l = 0; l < 12; l++) {
                int e = tid + l*256;
                int s = e >> 10, r = (e >> 3) & 127, ln = e & 7;
                const void* src = g_w2s + ((size_t)((s*9 + koff)*128 + r)*128 + icc*64 + ln*8);
                cpa16(sb + 16384u + (uint32_t)(s*16384) + swz((uint32_t)(r*128 + ln*16)), src, 16);
            }
            CP_COMMIT();
            CP_WAIT0();
            __syncthreads();

#pragma unroll
            for (int kk = 0; kk < 4; kk++) {
                uint32_t akb = (uint32_t)(kk*32) + a_kbsel;
                uint32_t a[2][4];
#pragma unroll
                for (int mi = 0; mi < 2; mi++)
                    ldsm4(a[mi][0], a[mi][1], a[mi][2], a[mi][3],
                          a_base[mi] + (akb ^ a_xor[mi]));
                uint32_t bkb = (uint32_t)(kk*32) + b_kbsel;
#pragma unroll
                for (int s = 0; s < 3; s++) {
                    uint32_t bs = sb + 16384u + (uint32_t)(s*16384);
#pragma unroll
                    for (int jp = 0; jp < 4; jp++) {
                        int rb = wn*64 + jp*16 + b_rl;
                        uint32_t b0, b1, b2, b3;
                        ldsm4(b0, b1, b2, b3,
                              bs + (uint32_t)(rb*128) + (bkb ^ (uint32_t)((rb & 7) << 4)));
                        hmma(acc[0][2*jp],   a[0], b0, b1);
                        hmma(acc[1][2*jp],   a[1], b0, b1);
                        hmma(acc[0][2*jp+1], a[0], b2, b3);
                        hmma(acc[1][2*jp+1], a[1], b2, b3);
                    }
                }
            }
            __syncthreads();
        }
    }

    int gid = lane >> 2, qid = lane & 3;
#pragma unroll
    for (int mi = 0; mi < 2; mi++) {
        int m = mbase + wm*32 + mi*16 + gid;
#pragma unroll
        for (int ni = 0; ni < 8; ni++) {
            int n = wn*64 + ni*8 + qid*2;
            *(float2*)(g_c2 + (size_t)m*128 + n)     = make_float2(acc[mi][ni][0], acc[mi][ni][1]);
            *(float2*)(g_c2 + (size_t)(m+8)*128 + n) = make_float2(acc[mi][ni][2], acc[mi][ni][3]);
        }
    }
}

// ============================================================
// BN2 + IF + pool -> g_s2
// ============================================================
__global__ void k_if2_pool(const float* __restrict__ b2,
                           const float* __restrict__ bg,
                           const float* __restrict__ bbta,
                           const float* __restrict__ bm,
                           const float* __restrict__ bv)
{
    int pos = blockIdx.x;
    int b = pos / 144, pp = pos % 144;
    int py = pp / 12, px = pp % 12;
    int oc = threadIdx.x;

    float scale = bg[oc] * rsqrtf(bv[oc] + 1e-5f);
    float add   = (b2[oc] - bm[oc]) * scale + bbta[oc];

    float v[4] = {0.f, 0.f, 0.f, 0.f};
#pragma unroll
    for (int t = 0; t < TT; t++) {
        float any = 0.f;
#pragma unroll
        for (int d = 0; d < 4; d++) {
            int m = (t*BB + b)*576 + (2*py + (d>>1))*24 + (2*px + (d&1));
            float xx = g_c2[(size_t)m*128 + oc] * scale + add;
            v[d] += xx;
            if (v[d] >= 1.0f) { any = 1.f; v[d] = 0.f; }
        }
        g_s2[((size_t)(t*BB + b)*144 + pp)*128 + oc] = __float2bfloat16(any);
    }
}

// ============================================================
// fc1 HMMA GEMM: FULL-M (M=256, 512 thr, 8 M-warps x 2 N-warps;
// each B tile read ONCE) + double-buffered k32 pipeline (SW64).
// grid (9 n-tiles, 16 slices) = 144 blocks = 1 wave.
// Smem: 2 x (A 16KB + 3xB 8KB) = 80KB.
// ============================================================
__global__ void __launch_bounds__(512, 1) k_fc1_mma()
{
    extern __shared__ unsigned char dsm[];
    uint32_t sb0 = smaddr(dsm);
    uint32_t sb  = (sb0 + 1023) & ~1023u;

    int tid = threadIdx.x, wid = tid >> 5, lane = tid & 31;
    int wm = wid & 7, wn = wid >> 3;

    int nbase = blockIdx.x * 128;
    int slice = blockIdx.y;
    int kbase = slice * (FC1_IN/NSLICE);   // 1152

    // fragment addressing (SW64, 64B rows)
    uint32_t a_fb[2], a_fx[2];
#pragma unroll
    for (int mi = 0; mi < 2; mi++) {
        int r = wm*32 + mi*16 + (lane & 15);          // 0..255
        a_fb[mi] = (uint32_t)(r*64);
        a_fx[mi] = (uint32_t)((r & 6) << 3);
    }
    uint32_t a_kbsel = (uint32_t)((lane >> 4) * 16);
    int b_rl = ((lane >> 4) & 1)*8 + (lane & 7);
    uint32_t b_kbsel = (uint32_t)(((lane >> 3) & 1) * 16);
    uint32_t b_fb[4], b_fx[4];
#pragma unroll
    for (int jp = 0; jp < 4; jp++) {
        int rb = wn*64 + jp*16 + b_rl;
        b_fb[jp] = (uint32_t)(rb*64);
        b_fx[jp] = (uint32_t)((rb & 6) << 3);
    }

    // staging precompute: 2560 chunks/stage, 5 per thread
    uint32_t st_src[5], st_dst[5];
    int st_isA[5];
#pragma unroll
    for (int l = 0; l < 5; l++) {
        int e = tid + l*512;
        if (e < 1024) {                 // A: 256 rows x 32k
            int r = e >> 2, ln = e & 3;
            st_isA[l] = 1;
            st_src[l] = (uint32_t)(r*FC1_IN + ln*8);
            st_dst[l] = swz64((uint32_t)(r*64 + ln*16));
        } else {                        // B: 3 splits x 128 n x 32k
            int eb = e - 1024;
            int s = eb >> 9, r = (eb >> 2) & 127, ln = eb & 3;
            st_isA[l] = 0;
            st_src[l] = (uint32_t)((uint32_t)s*(uint32_t)SZW1
                       + (uint32_t)((nbase + r)*FC1_IN + ln*8));
            st_dst[l] = (uint32_t)(F1_BOFF + s*8192) + swz64((uint32_t)(r*64 + ln*16));
        }
    }

    float acc[2][8][4];
#pragma unroll
    for (int i = 0; i < 2; i++)
#pragma unroll
        for (int j = 0; j < 8; j++)
#pragma unroll
            for (int k = 0; k < 4; k++) acc[i][j][k] = 0.f;

    auto issue = [&](int st) {
        uint32_t buf = sb + (uint32_t)((st & 1) * F1_STAGE);
        uint32_t kd = (uint32_t)(kbase + st*32);
#pragma unroll
        for (int l = 0; l < 5; l++) {
            const void* src = st_isA[l]
                ? (const void*)(g_s2 + (size_t)st_src[l] + kd)
                : (const void*)(g_w1s + (size_t)st_src[l] + kd);
            cpa16(buf + st_dst[l], src, 16);
        }
        CP_COMMIT();
    };

    issue(0);
    for (int st = 0; st < 36; st++) {
        if (st + 1 < 36) {
            issue(st + 1);
            CP_WAIT1();
        } else {
            CP_WAIT0();
        }
        __syncthreads();

        uint32_t buf = sb + (uint32_t)((st & 1) * F1_STAGE);
#pragma unroll
        for (int kk = 0; kk < 2; kk++) {
            uint32_t akb = (uint32_t)(kk*32) + a_kbsel;
            uint32_t a[2][4];
#pragma unroll
            for (int mi = 0; mi < 2; mi++)
                ldsm4(a[mi][0], a[mi][1], a[mi][2], a[mi][3],
                      buf + a_fb[mi] + (akb ^ a_fx[mi]));
            uint32_t bkb = (uint32_t)(kk*32) + b_kbsel;
#pragma unroll
            for (int s = 0; s < 3; s++) {
                uint32_t bsb = buf + (uint32_t)(F1_BOFF + s*8192);
#pragma unroll
                for (int jp = 0; jp < 4; jp++) {
                    uint32_t b0, b1, b2, b3;
                    ldsm4(b0, b1, b2, b3, bsb + b_fb[jp] + (bkb ^ b_fx[jp]));
                    hmma(acc[0][2*jp],   a[0], b0, b1);
                    hmma(acc[1][2*jp],   a[1], b0, b1);
                    hmma(acc[0][2*jp+1], a[0], b2, b3);
                    hmma(acc[1][2*jp+1], a[1], b2, b3);
                }
            }
        }
        __syncthreads();
    }

    int gid = lane >> 2, qid = lane & 3;
#pragma unroll
    for (int mi = 0; mi < 2; mi++) {
        int m = wm*32 + mi*16 + gid;
#pragma unroll
        for (int ni = 0; ni < 8; ni++) {
            int n = nbase + wn*64 + ni*8 + qid*2;
            float* dst = g_part1 + ((size_t)slice*NROWS + m)*FC1_OUT + n;
            *(float2*)dst = make_float2(acc[mi][ni][0], acc[mi][ni][1]);
            *(float2*)(dst + 8*FC1_OUT) = make_float2(acc[mi][ni][2], acc[mi][ni][3]);
        }
    }
}

// ============================================================
// fc2 scalar FFMA2 GEMM
// ============================================================
__global__ void __launch_bounds__(256)
k_gemm2(const float* __restrict__ Bmat, int N, int K, int klen)
{
    __shared__ float AsT[16][130];
    __shared__ float BsT[16][66];
    const float* A = g_l1;
    float* P = g_part2;

    int tid = threadIdx.x;
    int tx = tid & 15, ty = tid >> 4;
    int bm = blockIdx.y, bn = blockIdx.x, sz = blockIdx.z;
    int ks = sz * klen, ke = ks + klen;

    unsigned long long acc[4][4];
#pragma unroll
    for (int i = 0; i < 4; i++)
#pragma unroll
        for (int j = 0; j < 4; j++) acc[i][j] = 0ULL;

    for (int kk = ks; kk < ke; kk += 16) {
#pragma unroll
        for (int l = 0; l < 2; l++) {
            int lin = tid + l*256;
            int row = lin >> 2, cg = lin & 3;
            const float4 va = *reinterpret_cast<const float4*>(
                &A[(size_t)(bm*128 + row)*K + kk + cg*4]);
            AsT[cg*4 + 0][row] = va.x; AsT[cg*4 + 1][row] = va.y;
            AsT[cg*4 + 2][row] = va.z; AsT[cg*4 + 3][row] = va.w;
        }
        {
            int row = tid >> 2, cg = tid & 3;
            const float4 vb = *reinterpret_cast<const float4*>(
                &Bmat[(size_t)(bn*64 + row)*K + kk + cg*4]);
            BsT[cg*4 + 0][row] = vb.x; BsT[cg*4 + 1][row] = vb.y;
            BsT[cg*4 + 2][row] = vb.z; BsT[cg*4 + 3][row] = vb.w;
        }
        __syncthreads();
#pragma unroll
        for (int c = 0; c < 16; c++) {
            unsigned long long a2[4];
#pragma unroll
            for (int ip = 0; ip < 4; ip++)
                a2[ip] = *reinterpret_cast<const unsigned long long*>(&AsT[c][ty*8 + ip*2]);
            unsigned long long b2[4];
#pragma unroll
            for (int j = 0; j < 4; j++) {
                float bv = BsT[c][tx*4 + j];
                b2[j] = pk2(bv, bv);
            }
#pragma unroll
            for (int ip = 0; ip < 4; ip++)
#pragma unroll
                for (int j = 0; j < 4; j++)
                    acc[ip][j] = ffma2(a2[ip], b2[j], acc[ip][j]);
        }
        __syncthreads();
    }
#pragma unroll
    for (int ip = 0; ip < 4; ip++)
#pragma unroll
        for (int j = 0; j < 4; j++) {
            float2 u = upk2(acc[ip][j]);
            int row = bm*128 + ty*8 + ip*2;
            int col = bn*64 + tx*4 + j;
            P[(size_t)sz*NROWS*N + (size_t)row*N + col] = u.x;
            P[(size_t)sz*NROWS*N + (size_t)(row+1)*N + col] = u.y;
        }
}

// ============================================================
// Fused: split-K reduce + bias + LIF
// ============================================================
__global__ void k_reduce_lif(const float* __restrict__ bias, int which, int N, int S)
{
    const float* P = (which == 0) ? g_part1 : g_part2;
    float* L       = (which == 0) ? g_l1 : g_l2;
    int idx = blockIdx.x * blockDim.x + threadIdx.x;
    if (idx >= BB*N) return;
    int b = idx / N, o = idx % N;
    float bo = bias[o];
    float v = 0.f;
#pragma unroll 2
    for (int t = 0; t < TT; t++) {
        float s = bo;
        size_t base = (size_t)(t*BB + b)*N + o;
        for (int z = 0; z < S; z++) s += P[(size_t)z*NROWS*N + base];
        v += (s - v) * 0.5f;
        float sp = (v >= 1.0f) ? 1.f : 0.f;
        L[base] = sp;
        if (sp != 0.f) v = 0.f;
    }
}

// fc3 + LIF + mean over T
__global__ void k_fc3_lif_mean(const float* __restrict__ w,
                               const float* __restrict__ bias,
                               float* __restrict__ out)
{
    __shared__ float row[FC2_OUT];
    int b = blockIdx.x, tid = threadIdx.x;
    float v = 0.f, acc = 0.f;
#pragma unroll
    for (int t = 0; t < TT; t++) {
        for (int i = tid; i < FC2_OUT; i += 32)
            row[i] = g_l2[(size_t)(t*BB + b)*FC2_OUT + i];
        __syncthreads();
        if (tid < FC3_OUT) {
            float s = bias[tid];
#pragma unroll 8
            for (int i = 0; i < FC2_OUT; i++) s += row[i] * w[tid*FC2_OUT + i];
            v += (s - v) * 0.5f;
            if (v >= 1.0f) { acc += 1.f; v = 0.f; }
        }
        __syncthreads();
    }
    if (tid < FC3_OUT) out[b*FC3_OUT + tid] = acc * 0.125f;
}

// ============================================================
extern "C" void kernel_launch(void* const* d_in, const int* in_sizes, int n_in,
                              void* d_out, int out_size)
{
    const float* x       = (const float*)d_in[0];
    const float* conv1_w = (const float*)d_in[1];
    const float* conv1_b = (const float*)d_in[2];
    const float* bn1_g   = (const float*)d_in[3];
    const float* bn1_b   = (const float*)d_in[4];
    const float* bn1_m   = (const float*)d_in[5];
    const float* bn1_v   = (const float*)d_in[6];
    const float* conv2_w = (const float*)d_in[7];
    const float* conv2_b = (const float*)d_in[8];
    const float* bn2_g   = (const float*)d_in[9];
    const float* bn2_b   = (const float*)d_in[10];
    const float* bn2_m   = (const float*)d_in[11];
    const float* bn2_v   = (const float*)d_in[12];
    const float* fc1_w   = (const float*)d_in[13];
    const float* fc1_b   = (const float*)d_in[14];
    const float* fc2_w   = (const float*)d_in[15];
    const float* fc2_b   = (const float*)d_in[16];
    const float* fc3_w   = (const float*)d_in[17];
    const float* fc3_b   = (const float*)d_in[18];
    float* out = (float*)d_out;

    const int DSM    = 66560;           // conv2: 64KB tiles + 1KB align slack
    const int DSM_F1 = 2*F1_STAGE + 1024;  // fc1: 80KB + slack
    const int PW1_SMEM = 128*145*4;     // 74240
    cudaFuncSetAttribute(k_conv2_mma, cudaFuncAttributeMaxDynamicSharedMemorySize, DSM);
    cudaFuncSetAttribute(k_fc1_mma,  cudaFuncAttributeMaxDynamicSharedMemorySize, DSM_F1);
    cudaFuncSetAttribute(k_prep_w1,  cudaFuncAttributeMaxDynamicSharedMemorySize, PW1_SMEM);

    // ---- side stream for weight prep (capture-safe fork/join) ----
    cudaStream_t s1;
    cudaStreamCreateWithFlags(&s1, cudaStreamNonBlocking);
    cudaEvent_t eFork, eW2, eW1;
    cudaEventCreateWithFlags(&eFork, cudaEventDisableTiming);
    cudaEventCreateWithFlags(&eW2,   cudaEventDisableTiming);
    cudaEventCreateWithFlags(&eW1,   cudaEventDisableTiming);

    cudaEventRecord(eFork, 0);
    cudaStreamWaitEvent(s1, eFork, 0);

    // side stream: weight prep
    k_prep_w2<<<(128*128*9 + 255)/256, 256, 0, s1>>>(conv2_w);
    cudaEventRecord(eW2, s1);
    k_prep_w1<<<FC1_OUT, 256, PW1_SMEM, s1>>>(fc1_w);
    cudaEventRecord(eW1, s1);

    // main stream
    {
        int total = BB*P1S*P1S*128;
        k_conv1_if_pool<<<(total + 255)/256, 256>>>(x, conv1_w, conv1_b,
                                                    bn1_g, bn1_b, bn1_m, bn1_v);
    }
    cudaStreamWaitEvent(0, eW2, 0);
    k_conv2_mma<<<MTOT/128, 256, DSM>>>();
    k_if2_pool<<<BB*144, 128>>>(conv2_b, bn2_g, bn2_b, bn2_m, bn2_v);
    cudaStreamWaitEvent(0, eW1, 0);
    {
        dim3 g(FC1_OUT/128, NSLICE);
        k_fc1_mma<<<g, 512, DSM_F1>>>();
        int n = BB*FC1_OUT;
        k_reduce_lif<<<(n + 255)/256, 256>>>(fc1_b, 0, FC1_OUT, NSLICE);
    }
    {
        dim3 g(FC2_OUT/64, NROWS/128, 8);
        k_gemm2<<<g, 256>>>(fc2_w, FC2_OUT, FC1_OUT, FC1_OUT/8);
        int n = BB*FC2_OUT;
        k_reduce_lif<<<(n + 255)/256, 256>>>(fc2_b, 1, FC2_OUT, 8);
    }
    k_fc3_lif_mean<<<BB, 32>>>(fc3_w, fc3_b, out);
}